// round 17
// baseline (speedup 1.0000x reference)
#include <cuda_runtime.h>
#include <cuda_bf16.h>
#include <cstdint>

// out shape (256, 2, 512, 512) fp32.
// out[b,t,p,q] = sum_k vert[p,k]*hor[q,k]; factors pre-scaled by s=1/SIDE=1024/pi
// (absorbs /PIXEL_AREA exactly). fp32 factors split hi/lo into bf16;
// D = Ah*Bh + Ah*Bl + Al*Bh via mma.sync bf16 (fp32 accum).
//
// CTA: 128(p) x 128(q), 8 warps as 4(m) x 2(n), warp tile 32x64.
// K chunked by 16 with DOUBLE-BUFFERED smem tiles: fill(ks+1) overlaps
// ldmatrix+MMA(ks) in the same inter-sync region (ALU/STS vs MIO/tensor).
// Chunk tiles: [128 rows][16 k] bf16, row stride 48 B -> 8 consecutive
// ldmatrix rows hit 8 distinct 16B groups (48*r mod 128), conflict-free.

#define NTHREADS 256
#define CSTRIDE 48                      // bytes per chunk-tile row
#define CH_BYTES (128 * CSTRIDE)        // 6144
#define SM_SX   0
#define SM_SY   256
#define SM_T0   512                     // 8 chunk tiles follow
#define SMEM_TOTAL (SM_T0 + 8 * CH_BYTES)   // 49664 B

__device__ __forceinline__ float clamp01(float v) {
    return fminf(fmaxf(v, 0.0f), 1.0f);
}

__device__ __forceinline__ uint32_t smem_u32(const void* p) {
    uint32_t a;
    asm("{ .reg .u64 t; cvta.to.shared.u64 t, %1; cvt.u32.u64 %0, t; }"
        : "=r"(a) : "l"(p));
    return a;
}

// split v0,v1 into bf16 hi pair (v0 in low half) + bf16 lo residual pair
__device__ __forceinline__ void split2(float v0, float v1, uint32_t& h2, uint32_t& l2) {
    asm("cvt.rn.bf16x2.f32 %0, %1, %2;" : "=r"(h2) : "f"(v1), "f"(v0));
    float h0f = __uint_as_float(h2 << 16);
    float h1f = __uint_as_float(h2 & 0xFFFF0000u);
    float l0 = v0 - h0f;
    float l1 = v1 - h1f;
    asm("cvt.rn.bf16x2.f32 %0, %1, %2;" : "=r"(l2) : "f"(l1), "f"(l0));
}

__device__ __forceinline__ void ldmx4(uint32_t* r, uint32_t addr) {
    asm volatile(
        "ldmatrix.sync.aligned.m8n8.x4.shared.b16 {%0,%1,%2,%3}, [%4];"
        : "=r"(r[0]), "=r"(r[1]), "=r"(r[2]), "=r"(r[3]) : "r"(addr));
}

__device__ __forceinline__ void mma_bf16(float* d, const uint32_t* a,
                                         uint32_t b0, uint32_t b1) {
    asm volatile(
        "mma.sync.aligned.m16n8k16.row.col.f32.bf16.bf16.f32 "
        "{%0,%1,%2,%3}, {%4,%5,%6,%7}, {%8,%9}, {%0,%1,%2,%3};"
        : "+f"(d[0]), "+f"(d[1]), "+f"(d[2]), "+f"(d[3])
        : "r"(a[0]), "r"(a[1]), "r"(a[2]), "r"(a[3]), "r"(b0), "r"(b1));
}

// Fill one 16-k chunk (set = 0/1) for both A (vert) and B (hor) tiles.
// Thread decomposition: sel = tid>>7 (A/B), kp = (tid>>4)&7, rg = tid&15;
// each thread computes rows rg*8 .. rg*8+7 for its k-pair.
__device__ __forceinline__ void fill_chunk(
    char* smem, const float* sxs, const float* sys,
    int ks, int set, int t, int pTile, int qTile, int tid)
{
    const int sel = tid >> 7;
    const int kp = (tid >> 4) & 7;
    const int rg = tid & 15;
    const int k0 = ks * 16 + 2 * kp;
    const float x0 = sxs[k0],     y0 = sys[k0];
    const float x1 = sxs[k0 + 1], y1 = sys[k0 + 1];

    char* hbase = smem + SM_T0 + (set * 4 + (sel ? 2 : 0)) * CH_BYTES;
    char* lbase = hbase + CH_BYTES;
    uint32_t off = (uint32_t)(rg * 8) * CSTRIDE + kp * 4;

    if (sel == 0) {          // A = vert, rows are p
        #pragma unroll
        for (int i = 0; i < 8; i++) {
            int p = pTile + rg * 8 + i;
            float v0, v1;
            if (t == 0) {
                float f512p = (float)(512 - p), fp1 = (float)(p + 1);
                v0 = clamp01(fminf(f512p - y0, x0 + fp1));
                v1 = clamp01(fminf(f512p - y1, x1 + fp1));
            } else {
                float f511p = (float)(511 - p);
                v0 = clamp01(y0 - f511p);
                v1 = clamp01(y1 - f511p);
            }
            uint32_t h2, l2;
            split2(v0, v1, h2, l2);
            *(uint32_t*)(hbase + off + i * CSTRIDE) = h2;
            *(uint32_t*)(lbase + off + i * CSTRIDE) = l2;
        }
    } else {                 // B = hor, rows are q
        #pragma unroll
        for (int i = 0; i < 8; i++) {
            int q = qTile + rg * 8 + i;
            float fq1 = (float)(q + 1);
            float v0, v1;
            if (t == 0) {
                float fq = (float)q;
                v0 = clamp01(fminf(fq1 - x0, y0 - fq));
                v1 = clamp01(fminf(fq1 - x1, y1 - fq));
            } else {
                v0 = clamp01(fq1 - x0);
                v1 = clamp01(fq1 - x1);
            }
            uint32_t h2, l2;
            split2(v0, v1, h2, l2);
            *(uint32_t*)(hbase + off + i * CSTRIDE) = h2;
            *(uint32_t*)(lbase + off + i * CSTRIDE) = l2;
        }
    }
}

__global__ __launch_bounds__(NTHREADS, 2)
void raster_hmma(const float* __restrict__ in00,
                 const float* __restrict__ in01,
                 float* __restrict__ out)
{
    extern __shared__ char smem[];
    const uint32_t smem_base = smem_u32(smem);
    const int tid = threadIdx.x;
    const int lane = tid & 31;
    const int wid = tid >> 5;

    const int qTile = blockIdx.x * 128;
    const int pTile = blockIdx.y * 128;
    const int z = blockIdx.z;          // b*2 + t
    const int b = z >> 1;
    const int t = z & 1;
    const int K = t ? 32 : 64;
    const float S = 325.94932345220164f;  // 1024/pi

    float* sxs = (float*)(smem + SM_SX);
    float* sys = (float*)(smem + SM_SY);
    if (tid < K) {
        float x, y;
        if (t == 0) {
            if (tid < 32) {
                x = S * in00[b * 64 + 2 * tid];             // s*a0
                y = S * in00[b * 64 + 2 * tid + 1];         // s*b0
            } else {
                int j = tid - 32;
                x = S * in01[b * 64 + 2 * j + 1] - 512.0f;  // s*b1 - 512
                y = S * in01[b * 64 + 2 * j];               // s*a1
            }
        } else {
            x = S * in00[b * 64 + 2 * tid];
            y = S * in00[b * 64 + 2 * tid + 1];
        }
        sxs[tid] = x;
        sys[tid] = y;
    }
    __syncthreads();

    // ---- Warp tiling + ldmatrix addressing (within a chunk tile) ----
    const int wm = wid & 3;                // warp row (m): 4 x 32
    const int wn = wid >> 2;               // warp col (n): 2 x 64
    const uint32_t a_off = (uint32_t)(wm * 32 + (lane & 15)) * CSTRIDE
                         + (uint32_t)(lane >> 4) * 16;
    const uint32_t b_off = (uint32_t)(wn * 64 + ((lane >> 4) << 3) + (lane & 7)) * CSTRIDE
                         + (uint32_t)((lane >> 3) & 1) * 16;

    float acc[2][8][4];
    #pragma unroll
    for (int mb = 0; mb < 2; mb++)
        #pragma unroll
        for (int nb = 0; nb < 8; nb++)
            #pragma unroll
            for (int r = 0; r < 4; r++)
                acc[mb][nb][r] = 0.0f;

    const int nks = K >> 4;                // 4 (hf) or 2 (ri)

    fill_chunk(smem, sxs, sys, 0, 0, t, pTile, qTile, tid);
    __syncthreads();

    for (int ks = 0; ks < nks; ks++) {
        const int cur = ks & 1;
        // Overlap: next chunk's fill issues alongside this chunk's MMA.
        if (ks + 1 < nks)
            fill_chunk(smem, sxs, sys, ks + 1, cur ^ 1, t, pTile, qTile, tid);

        const uint32_t base = smem_base + SM_T0 + (uint32_t)(cur * 4) * CH_BYTES;
        const uint32_t aAh = base + a_off;
        const uint32_t aAl = base + CH_BYTES + a_off;
        const uint32_t aBh = base + 2 * CH_BYTES + b_off;
        const uint32_t aBl = base + 3 * CH_BYTES + b_off;

        uint32_t Ah[2][4], Al[2][4];
        ldmx4(Ah[0], aAh);
        ldmx4(Ah[1], aAh + 16 * CSTRIDE);
        ldmx4(Al[0], aAl);
        ldmx4(Al[1], aAl + 16 * CSTRIDE);
        #pragma unroll
        for (int nblk = 0; nblk < 4; nblk++) {
            uint32_t Bh[4], Bl[4];
            ldmx4(Bh, aBh + nblk * 16 * CSTRIDE);
            ldmx4(Bl, aBl + nblk * 16 * CSTRIDE);
            #pragma unroll
            for (int mb = 0; mb < 2; mb++) {
                float* d0 = acc[mb][2 * nblk + 0];
                float* d1 = acc[mb][2 * nblk + 1];
                mma_bf16(d0, Ah[mb], Bh[0], Bh[1]);
                mma_bf16(d0, Al[mb], Bh[0], Bh[1]);
                mma_bf16(d0, Ah[mb], Bl[0], Bl[1]);
                mma_bf16(d1, Ah[mb], Bh[2], Bh[3]);
                mma_bf16(d1, Al[mb], Bh[2], Bh[3]);
                mma_bf16(d1, Ah[mb], Bl[2], Bl[3]);
            }
        }
        __syncthreads();
    }

    // ---- Epilogue: d0,d1 -> (row g, cols 2tig,2tig+1); d2,d3 -> row g+8 ----
    const int g = lane >> 2;
    const int tig = lane & 3;
    #pragma unroll
    for (int mb = 0; mb < 2; mb++) {
        int prow = pTile + wm * 32 + mb * 16 + g;
        float* o = out + (size_t)z * 262144 + (size_t)prow * 512
                 + (qTile + wn * 64 + 2 * tig);
        #pragma unroll
        for (int nb = 0; nb < 8; nb++) {
            __stcs((float2*)(o + nb * 8),
                   make_float2(acc[mb][nb][0], acc[mb][nb][1]));
            __stcs((float2*)(o + 8 * 512 + nb * 8),
                   make_float2(acc[mb][nb][2], acc[mb][nb][3]));
        }
    }
}

extern "C" void kernel_launch(void* const* d_in, const int* in_sizes, int n_in,
                              void* d_out, int out_size)
{
    const float* in00 = (const float*)d_in[0];  // intervals00 (256,32,2)
    const float* in01 = (const float*)d_in[1];  // intervals01 (256,32,2)
    float* out = (float*)d_out;                 // (256,2,512,512)

    cudaFuncSetAttribute(raster_hmma,
                         cudaFuncAttributeMaxDynamicSharedMemorySize, SMEM_TOTAL);
    dim3 grid(4, 4, 512);
    raster_hmma<<<grid, NTHREADS, SMEM_TOTAL>>>(in00, in01, out);
}